// round 15
// baseline (speedup 1.0000x reference)
#include <cuda_runtime.h>
#include <cuda_fp16.h>
#include <cstdint>
#include <cstddef>

// ===========================================================================
// InvariantReadout — fp16 1-MMA HMMA, round 15
//   64x64 warp tile (4 warps, 128 thr, 2 CTAs/SM): 8 LDSM per 32 HMMA
//   halves L1 pressure (was tensor=48%, L1=75% with 32x64 tiles).
//   h1 = silu(X@W1+b1); h2 = silu(h1@W2+b2); x = h2@W3+b3 (never stored)
//   logits via GEMM1 att parts; weights standalone (single-pass);
//   readout fused in GEMM3 epilogue (register+shuffle reduction).
// ===========================================================================

#define NMAX 200000
#define DIM  256
#define BM   128
#define BN   128
#define BKT  64
#define KTILES (DIM / BKT)            // 4
#define OFF_B    16384
#define STAGE    32768
#define NSTAGE   3
#define DYN_SMEM (NSTAGE * STAGE)     // 96 KB -> 2 CTAs/SM
#define TILESMAX ((NMAX + BM - 1) / BM)

#define SP_NONE 0
#define SP_ATT  1   // parts 2,3 = attention epilogue

// ---------------- scratch ---------------------------------------------------
__device__ __half g_Xh[(size_t)NMAX * DIM];
__device__ __half g_h1[(size_t)NMAX * DIM];
__device__ __half g_h2[(size_t)NMAX * DIM];
__device__ float  g_att[2][NMAX];
__device__ float  g_w[NMAX];
__device__ float  g_rpart[(size_t)TILESMAX * 2 * DIM];
__device__ __half g_Wt[4][DIM * DIM];         // {W1,W2,W3,aW1} fp16, n-major

// ---------------- helpers ---------------------------------------------------
__device__ __forceinline__ uint32_t smem_u32(const void* p) {
    uint32_t a;
    asm("{ .reg .u64 t; cvta.to.shared.u64 t, %1; cvt.u32.u64 %0, t; }" : "=r"(a) : "l"(p));
    return a;
}
__device__ __forceinline__ void cp16(uint32_t dst, const void* src) {
    asm volatile("cp.async.cg.shared.global [%0], [%1], 16;" :: "r"(dst), "l"(src) : "memory");
}
__device__ __forceinline__ void cp_commit() {
    asm volatile("cp.async.commit_group;" ::: "memory");
}
template <int NW>
__device__ __forceinline__ void cp_wait() {
    asm volatile("cp.async.wait_group %0;" :: "n"(NW) : "memory");
}
__device__ __forceinline__ void ldsm4(uint32_t* r, uint32_t addr) {
    asm volatile("ldmatrix.sync.aligned.m8n8.x4.shared.b16 {%0,%1,%2,%3}, [%4];"
                 : "=r"(r[0]), "=r"(r[1]), "=r"(r[2]), "=r"(r[3]) : "r"(addr));
}
__device__ __forceinline__ void mma16816(float* d, const uint32_t* a, const uint32_t* b) {
    asm volatile(
        "mma.sync.aligned.m16n8k16.row.col.f32.f16.f16.f32 "
        "{%0,%1,%2,%3}, {%4,%5,%6,%7}, {%8,%9}, {%0,%1,%2,%3};"
        : "+f"(d[0]), "+f"(d[1]), "+f"(d[2]), "+f"(d[3])
        : "r"(a[0]), "r"(a[1]), "r"(a[2]), "r"(a[3]), "r"(b[0]), "r"(b[1]));
}
__device__ __forceinline__ float silu_f(float x) { return x / (1.0f + __expf(-x)); }
__device__ __forceinline__ uint32_t h2_as_u32(__half2 h) {
    uint32_t u;
    *(__half2*)&u = h;
    return u;
}
__device__ __forceinline__ int lower_bound_i(const int* __restrict__ a, int n, int v) {
    int lo = 0, hi = n;
    while (lo < hi) { int m = (lo + hi) >> 1; if (a[m] < v) lo = m + 1; else hi = m; }
    return lo;
}

// ---------------- prep: X fp32->fp16 + weight transpose, one launch ---------
__global__ __launch_bounds__(256) void prep_kernel(
    const float4* __restrict__ X, uint2* __restrict__ Xh, int n4,
    const float* __restrict__ W1, const float* __restrict__ W2,
    const float* __restrict__ W3, const float* __restrict__ WA,
    __half* __restrict__ Wt)
{
    if (blockIdx.x < 1024) {
        int w = blockIdx.x >> 8;
        int n = blockIdx.x & 255;
        int k = threadIdx.x;
        const float* W = (w == 0) ? W1 : (w == 1) ? W2 : (w == 2) ? W3 : WA;
        Wt[(size_t)w * DIM * DIM + n * DIM + k] = __float2half_rn(W[k * DIM + n]);
        return;
    }
    int i = (blockIdx.x - 1024) * 256 + threadIdx.x;
    if (i >= n4) return;
    float4 v = X[i];
    Xh[i] = make_uint2(h2_as_u32(__floats2half2_rn(v.x, v.y)),
                       h2_as_u32(__floats2half2_rn(v.z, v.w)));
}

// weights: per-segment softmax (single-pass when len<=256)
__global__ __launch_bounds__(256) void weights_kernel(
    const float* __restrict__ p0, const float* __restrict__ p1,
    const float* __restrict__ ab2, const int* __restrict__ batch,
    float* __restrict__ wout, int nRows)
{
    const int g = blockIdx.x, t = threadIdx.x;
    __shared__ float red[256];
    __shared__ int   srange[2];
    if (t == 0) srange[0] = lower_bound_i(batch, nRows, g);
    if (t == 1) srange[1] = lower_bound_i(batch, nRows, g + 1);
    __syncthreads();
    const int start = srange[0], end = srange[1];
    if (start >= end) return;
    const float bb = ab2[0];
    const int len = end - start;
    if (len <= 256) {
        const int i = start + t;
        float lg = (i < end) ? p0[i] + p1[i] + bb : -3.402823466e38f;
        red[t] = lg; __syncthreads();
        #pragma unroll
        for (int s = 128; s; s >>= 1) {
            if (t < s) red[t] = fmaxf(red[t], red[t + s]);
            __syncthreads();
        }
        const float m = red[0]; __syncthreads();
        float e = (i < end) ? __expf(lg - m) : 0.f;
        red[t] = e; __syncthreads();
        #pragma unroll
        for (int s = 128; s; s >>= 1) {
            if (t < s) red[t] += red[t + s];
            __syncthreads();
        }
        if (i < end) wout[i] = e / red[0];
    } else {
        float m = -3.402823466e38f;
        for (int i = start + t; i < end; i += 256)
            m = fmaxf(m, p0[i] + p1[i] + bb);
        red[t] = m; __syncthreads();
        #pragma unroll
        for (int s = 128; s; s >>= 1) {
            if (t < s) red[t] = fmaxf(red[t], red[t + s]);
            __syncthreads();
        }
        m = red[0]; __syncthreads();
        float ssum = 0.f;
        for (int i = start + t; i < end; i += 256)
            ssum += __expf(p0[i] + p1[i] + bb - m);
        red[t] = ssum; __syncthreads();
        #pragma unroll
        for (int s = 128; s; s >>= 1) {
            if (t < s) red[t] += red[t + s];
            __syncthreads();
        }
        const float inv = 1.0f / red[0];
        for (int i = start + t; i < end; i += 256)
            wout[i] = __expf(p0[i] + p1[i] + bb - m) * inv;
    }
}

// combine per-tile partials -> out (deterministic fixed-order sum)
__global__ __launch_bounds__(256) void combine_kernel(
    const float* __restrict__ rpart, const int* __restrict__ batch,
    float* __restrict__ out, int nRows)
{
    const int g = blockIdx.x, c = threadIdx.x;
    __shared__ int srange[2];
    if (c == 0) srange[0] = lower_bound_i(batch, nRows, g);
    if (c == 1) srange[1] = lower_bound_i(batch, nRows, g + 1);
    __syncthreads();
    const int lb = srange[0], ub = srange[1];
    float sum = 0.f;
    if (lb < ub) {
        int t0 = lb >> 7, t1 = (ub - 1) >> 7;
        for (int t = t0; t <= t1; t++) {
            int base_row = t << 7;
            int s0 = batch[base_row < nRows ? base_row : nRows - 1];
            int slot = g - s0;
            if (slot == 0 || slot == 1)
                sum += rpart[((size_t)t * 2 + slot) * DIM + c];
        }
    }
    out[(size_t)g * DIM + c] = sum;
}

// ---------------- fused GEMM: 4 warps, 64x64 warp tile ----------------------
// grid(nparts, tiles); blockIdx.x = part (fast -> A L2 reuse).
// SP_ATT: parts 2,3 attention epilogue on B1/bias1.
// rpart != nullptr: weighted-readout epilogue (register+shuffle reduce).
template <int SPECIAL>
__global__ __launch_bounds__(128, 2) void gemm_mma(
    const __half* __restrict__ A,
    const __half* __restrict__ B0, const __half* __restrict__ B1,
    const float* __restrict__ bias0, const float* __restrict__ bias1,
    __half* __restrict__ Ch,
    const float* __restrict__ aW2, float* __restrict__ attp,
    const int* __restrict__ batch, const float* __restrict__ wvec,
    float* __restrict__ rpart,
    int nRows, int do_silu)
{
    extern __shared__ char sm[];
    __shared__ float s_bias[BN];
    __shared__ float s_aw2[BN];
    __shared__ float s_part[2][BM];
    __shared__ float s_w[BM];
    __shared__ int   s_seg[BM];
    __shared__ float s_red[2][2][BN];

    const int tid  = threadIdx.x;
    const int wid  = tid >> 5;
    const int lane = tid & 31;
    const int warp_m = wid >> 1;        // 0..1 -> 64-row slab
    const int warp_n = wid & 1;         // 0..1 -> 64-col slab
    const int part = blockIdx.x;
    const bool is_att = (SPECIAL == SP_ATT) && (part >= 2);
    const int colBase = (part & 1) * BN;
    const int rowBase = blockIdx.y * BM;

    const __half* B    = is_att ? B1 : B0;
    const float*  bias = is_att ? bias1 : bias0;

    s_bias[tid] = bias[colBase + tid];
    if (is_att) s_aw2[tid] = aW2[colBase + tid];
    if (rpart) {
        int row = rowBase + tid;
        int cr  = row < nRows ? row : nRows - 1;
        s_w[tid]   = (row < nRows) ? wvec[row] : 0.f;
        s_seg[tid] = batch[cr];
    }

    const uint32_t smb = smem_u32(sm);

    auto load_stage = [&](int s, int kt) {
        const uint32_t st = smb + s * STAGE;
        const int ke = kt * BKT;
        #pragma unroll
        for (int i = 0; i < 8; i++) {
            int f = tid + i * 128;
            int r = f >> 3, c = f & 7;
            uint32_t off = (uint32_t)(r * 128 + ((c ^ (r & 7)) << 4));
            int gr = rowBase + r; if (gr >= nRows) gr = nRows - 1;
            cp16(st + off,         A + (size_t)gr * DIM + ke + c * 8);
            cp16(st + OFF_B + off, B + (size_t)(colBase + r) * DIM + ke + c * 8);
        }
        cp_commit();
    };

    load_stage(0, 0);
    load_stage(1, 1);

    float acc[4][8][4];
    #pragma unroll
    for (int mt = 0; mt < 4; mt++)
        #pragma unroll
        for (int j = 0; j < 8; j++)
            #pragma unroll
            for (int q = 0; q < 4; q++) acc[mt][j][q] = 0.f;

    const int rrA = (lane & 7) + ((lane >> 3) & 1) * 8;
    const int khA = lane >> 4;
    const int rrB = (lane & 7) + (lane >> 4) * 8;
    const int khB = (lane >> 3) & 1;

    int sbuf = 0;
    for (int kt = 0; kt < KTILES; kt++) {
        cp_wait<1>();
        __syncthreads();
        if (kt + 2 < KTILES) {
            int ns = sbuf + 2; if (ns >= NSTAGE) ns -= NSTAGE;
            load_stage(ns, kt + 2);
        } else {
            cp_commit();
        }

        const uint32_t ast = smb + sbuf * STAGE;

        #pragma unroll
        for (int ks = 0; ks < 4; ks++) {
            const int cA = ks * 2 + khA;
            const int cB = ks * 2 + khB;
            uint32_t ah[4][4];
            #pragma unroll
            for (int mt = 0; mt < 4; mt++) {
                int row = warp_m * 64 + mt * 16 + rrA;
                ldsm4(ah[mt], ast + row * 128 + ((cA ^ (row & 7)) << 4));
            }
            #pragma unroll
            for (int nt = 0; nt < 4; nt++) {
                int row = warp_n * 64 + nt * 16 + rrB;
                uint32_t bh[4];
                ldsm4(bh, ast + OFF_B + row * 128 + ((cB ^ (row & 7)) << 4));
                #pragma unroll
                for (int mt = 0; mt < 4; mt++)
                    #pragma unroll
                    for (int h = 0; h < 2; h++)
                        mma16816(acc[mt][nt * 2 + h], ah[mt], &bh[h * 2]);
            }
        }
        if (++sbuf >= NSTAGE) sbuf = 0;
    }

    // ---- epilogue ----
    const int g  = lane >> 2;
    const int cp = (lane & 3) * 2;

    if (is_att) {
        float pacc[4][2];
        #pragma unroll
        for (int mt = 0; mt < 4; mt++) { pacc[mt][0] = 0.f; pacc[mt][1] = 0.f; }
        #pragma unroll
        for (int mt = 0; mt < 4; mt++)
            #pragma unroll
            for (int j = 0; j < 8; j++) {
                int lc = warp_n * 64 + j * 8 + cp;
                float bz0 = s_bias[lc], bz1 = s_bias[lc + 1];
                float w0 = s_aw2[lc],  w1 = s_aw2[lc + 1];
                #pragma unroll
                for (int hrow = 0; hrow < 2; hrow++) {
                    float v0 = silu_f(acc[mt][j][hrow * 2]     + bz0);
                    float v1 = silu_f(acc[mt][j][hrow * 2 + 1] + bz1);
                    pacc[mt][hrow] += v0 * w0 + v1 * w1;
                }
            }
        #pragma unroll
        for (int mt = 0; mt < 4; mt++)
            #pragma unroll
            for (int hrow = 0; hrow < 2; hrow++) {
                float p = pacc[mt][hrow];
                p += __shfl_xor_sync(0xFFFFFFFFu, p, 1);
                p += __shfl_xor_sync(0xFFFFFFFFu, p, 2);
                if ((lane & 3) == 0)
                    s_part[warp_n][warp_m * 64 + mt * 16 + hrow * 8 + g] = p;
            }
        __syncthreads();
        {
            int row = rowBase + tid;
            if (row < nRows)
                attp[(size_t)(part - 2) * NMAX + row] =
                    s_part[0][tid] + s_part[1][tid];
        }
        return;
    }

    if (rpart) {
        const int sbase = s_seg[0];
        #pragma unroll
        for (int j = 0; j < 8; j++) {
            int lc = warp_n * 64 + j * 8 + cp;
            float bz0 = s_bias[lc], bz1 = s_bias[lc + 1];
            float a00 = 0.f, a10 = 0.f, a01 = 0.f, a11 = 0.f;
            #pragma unroll
            for (int mt = 0; mt < 4; mt++)
                #pragma unroll
                for (int hrow = 0; hrow < 2; hrow++) {
                    int lr = warp_m * 64 + mt * 16 + hrow * 8 + g;
                    float wv = s_w[lr];
                    float v0 = (acc[mt][j][hrow * 2]     + bz0) * wv;
                    float v1 = (acc[mt][j][hrow * 2 + 1] + bz1) * wv;
                    if (s_seg[lr] == sbase) { a00 += v0; a01 += v1; }
                    else                    { a10 += v0; a11 += v1; }
                }
            #pragma unroll
            for (int off = 4; off <= 16; off <<= 1) {
                a00 += __shfl_xor_sync(0xFFFFFFFFu, a00, off);
                a10 += __shfl_xor_sync(0xFFFFFFFFu, a10, off);
                a01 += __shfl_xor_sync(0xFFFFFFFFu, a01, off);
                a11 += __shfl_xor_sync(0xFFFFFFFFu, a11, off);
            }
            if ((lane >> 2) == 0) {
                s_red[warp_m][0][lc]     = a00;
                s_red[warp_m][1][lc]     = a10;
                s_red[warp_m][0][lc + 1] = a01;
                s_red[warp_m][1][lc + 1] = a11;
            }
        }
        __syncthreads();
        {
            size_t base = ((size_t)blockIdx.y * 2) * DIM + colBase + tid;
            rpart[base]       = s_red[0][0][tid] + s_red[1][0][tid];
            rpart[base + DIM] = s_red[0][1][tid] + s_red[1][1][tid];
        }
        return;
    }

    #pragma unroll
    for (int mt = 0; mt < 4; mt++) {
        int row0 = rowBase + warp_m * 64 + mt * 16 + g;
        #pragma unroll
        for (int j = 0; j < 8; j++) {
            int lc = warp_n * 64 + j * 8 + cp;
            float bz0 = s_bias[lc], bz1 = s_bias[lc + 1];
            #pragma unroll
            for (int hrow = 0; hrow < 2; hrow++) {
                int row = row0 + hrow * 8;
                if (row >= nRows) continue;
                float v0 = acc[mt][j][hrow * 2]     + bz0;
                float v1 = acc[mt][j][hrow * 2 + 1] + bz1;
                if (do_silu) { v0 = silu_f(v0); v1 = silu_f(v1); }
                size_t o = (size_t)row * DIM + colBase + lc;
                *(uint32_t*)(Ch + o) = h2_as_u32(__floats2half2_rn(v0, v1));
            }
        }
    }
}

// ---------------- launch ----------------------------------------------------
extern "C" void kernel_launch(void* const* d_in, const int* in_sizes, int n_in,
                              void* d_out, int out_size)
{
    const float* X     = (const float*)d_in[0];
    const int*   batch = (const int*)d_in[1];
    const float* W1  = (const float*)d_in[3];
    const float* b1  = (const float*)d_in[4];
    const float* W2  = (const float*)d_in[5];
    const float* b2  = (const float*)d_in[6];
    const float* W3  = (const float*)d_in[7];
    const float* b3  = (const float*)d_in[8];
    const float* aW1 = (const float*)d_in[9];
    const float* ab1 = (const float*)d_in[10];
    const float* aW2 = (const float*)d_in[11];
    const float* ab2 = (const float*)d_in[12];
    float* out = (float*)d_out;

    const int N = in_sizes[0] / DIM;
    const int G = out_size / DIM;

    __half *Xh, *h1, *h2, *Wt;
    float *att, *wv, *rp;
    cudaGetSymbolAddress((void**)&Xh, g_Xh);
    cudaGetSymbolAddress((void**)&h1, g_h1);
    cudaGetSymbolAddress((void**)&h2, g_h2);
    cudaGetSymbolAddress((void**)&Wt, g_Wt);
    cudaGetSymbolAddress((void**)&att, g_att);
    cudaGetSymbolAddress((void**)&wv, g_w);
    cudaGetSymbolAddress((void**)&rp, g_rpart);

    __half* W1t = Wt + 0 * DIM * DIM;
    __half* W2t = Wt + 1 * DIM * DIM;
    __half* W3t = Wt + 2 * DIM * DIM;
    __half* WAt = Wt + 3 * DIM * DIM;

    cudaFuncSetAttribute(gemm_mma<SP_ATT>,
                         cudaFuncAttributeMaxDynamicSharedMemorySize, DYN_SMEM);
    cudaFuncSetAttribute(gemm_mma<SP_NONE>,
                         cudaFuncAttributeMaxDynamicSharedMemorySize, DYN_SMEM);

    // prep: X conversion + weight transpose in one launch
    int n4 = N * (DIM / 4);
    prep_kernel<<<1024 + (n4 + 255) / 256, 256>>>(
        (const float4*)X, (uint2*)Xh, n4, W1, W2, W3, aW1, Wt);

    const int tiles = (N + BM - 1) / BM;

    // GEMM1: parts 0,1 -> h1; parts 2,3 -> att partials
    gemm_mma<SP_ATT><<<dim3(4, tiles), 128, DYN_SMEM>>>(
        Xh, W1t, WAt, b1, ab1, h1, aW2, att,
        nullptr, nullptr, nullptr, N, 1);

    // softmax weights (single-pass per segment)
    weights_kernel<<<G, 256>>>(att, att + NMAX, ab2, batch, wv, N);

    // GEMM2: h2 = silu(h1@W2+b2)
    gemm_mma<SP_NONE><<<dim3(2, tiles), 128, DYN_SMEM>>>(
        h1, W2t, W2t, b2, b2, h2, aW2, att,
        nullptr, nullptr, nullptr, N, 1);

    // GEMM3 + fused weighted readout partials
    gemm_mma<SP_NONE><<<dim3(2, tiles), 128, DYN_SMEM>>>(
        h2, W3t, W3t, b3, b3, nullptr, aW2, att,
        batch, wv, rp, N, 0);

    // deterministic combine -> out
    combine_kernel<<<G, 256>>>(rp, batch, out, N);
}

// round 16
// speedup vs baseline: 1.3153x; 1.3153x over previous
#include <cuda_runtime.h>
#include <cuda_fp16.h>
#include <cstdint>
#include <cstddef>

// ===========================================================================
// InvariantReadout — fp16 1-MMA HMMA, round 16 (= R12 + merged prep +
//   single-pass weights kernel; R15's 64x64 warp tile reverted).
//   h1 = silu(X@W1+b1); h2 = silu(h1@W2+b2); x = h2@W3+b3 (never stored)
//   logits via GEMM1 att parts; weights standalone single-pass;
//   readout fused in GEMM3 epilogue; deterministic combine.
// ===========================================================================

#define NMAX 200000
#define DIM  256
#define BM   128
#define BN   128
#define BKT  64
#define KTILES (DIM / BKT)            // 4
#define OFF_B    16384
#define STAGE    32768
#define NSTAGE   3
#define DYN_SMEM (NSTAGE * STAGE)     // 96 KB -> 2 CTAs/SM
#define TILESMAX ((NMAX + BM - 1) / BM)
#define XW_STRIDE 130

#define SP_NONE 0
#define SP_ATT  1   // parts 2,3 = attention epilogue

// ---------------- scratch ---------------------------------------------------
__device__ __half g_Xh[(size_t)NMAX * DIM];
__device__ __half g_h1[(size_t)NMAX * DIM];
__device__ __half g_h2[(size_t)NMAX * DIM];
__device__ float  g_att[2][NMAX];
__device__ float  g_w[NMAX];
__device__ float  g_rpart[(size_t)TILESMAX * 2 * DIM];
__device__ __half g_Wt[4][DIM * DIM];         // {W1,W2,W3,aW1} fp16, n-major

// ---------------- helpers ---------------------------------------------------
__device__ __forceinline__ uint32_t smem_u32(const void* p) {
    uint32_t a;
    asm("{ .reg .u64 t; cvta.to.shared.u64 t, %1; cvt.u32.u64 %0, t; }" : "=r"(a) : "l"(p));
    return a;
}
__device__ __forceinline__ void cp16(uint32_t dst, const void* src) {
    asm volatile("cp.async.cg.shared.global [%0], [%1], 16;" :: "r"(dst), "l"(src) : "memory");
}
__device__ __forceinline__ void cp_commit() {
    asm volatile("cp.async.commit_group;" ::: "memory");
}
template <int NW>
__device__ __forceinline__ void cp_wait() {
    asm volatile("cp.async.wait_group %0;" :: "n"(NW) : "memory");
}
__device__ __forceinline__ void ldsm4(uint32_t* r, uint32_t addr) {
    asm volatile("ldmatrix.sync.aligned.m8n8.x4.shared.b16 {%0,%1,%2,%3}, [%4];"
                 : "=r"(r[0]), "=r"(r[1]), "=r"(r[2]), "=r"(r[3]) : "r"(addr));
}
__device__ __forceinline__ void mma16816(float* d, const uint32_t* a, const uint32_t* b) {
    asm volatile(
        "mma.sync.aligned.m16n8k16.row.col.f32.f16.f16.f32 "
        "{%0,%1,%2,%3}, {%4,%5,%6,%7}, {%8,%9}, {%0,%1,%2,%3};"
        : "+f"(d[0]), "+f"(d[1]), "+f"(d[2]), "+f"(d[3])
        : "r"(a[0]), "r"(a[1]), "r"(a[2]), "r"(a[3]), "r"(b[0]), "r"(b[1]));
}
__device__ __forceinline__ float silu_f(float x) { return x / (1.0f + __expf(-x)); }
__device__ __forceinline__ uint32_t h2_as_u32(__half2 h) {
    uint32_t u;
    *(__half2*)&u = h;
    return u;
}
__device__ __forceinline__ int lower_bound_i(const int* __restrict__ a, int n, int v) {
    int lo = 0, hi = n;
    while (lo < hi) { int m = (lo + hi) >> 1; if (a[m] < v) lo = m + 1; else hi = m; }
    return lo;
}

// ---------------- prep: X fp32->fp16 + weight transpose, one launch ---------
__global__ __launch_bounds__(256) void prep_kernel(
    const float4* __restrict__ X, uint2* __restrict__ Xh, int n4,
    const float* __restrict__ W1, const float* __restrict__ W2,
    const float* __restrict__ W3, const float* __restrict__ WA,
    __half* __restrict__ Wt)
{
    if (blockIdx.x < 1024) {
        int w = blockIdx.x >> 8;
        int n = blockIdx.x & 255;
        int k = threadIdx.x;
        const float* W = (w == 0) ? W1 : (w == 1) ? W2 : (w == 2) ? W3 : WA;
        Wt[(size_t)w * DIM * DIM + n * DIM + k] = __float2half_rn(W[k * DIM + n]);
        return;
    }
    int i = (blockIdx.x - 1024) * 256 + threadIdx.x;
    if (i >= n4) return;
    float4 v = X[i];
    Xh[i] = make_uint2(h2_as_u32(__floats2half2_rn(v.x, v.y)),
                       h2_as_u32(__floats2half2_rn(v.z, v.w)));
}

// weights: per-segment softmax (single-pass when len<=256)
__global__ __launch_bounds__(256) void weights_kernel(
    const float* __restrict__ p0, const float* __restrict__ p1,
    const float* __restrict__ ab2, const int* __restrict__ batch,
    float* __restrict__ wout, int nRows)
{
    const int g = blockIdx.x, t = threadIdx.x;
    __shared__ float red[256];
    __shared__ int   srange[2];
    if (t == 0) srange[0] = lower_bound_i(batch, nRows, g);
    if (t == 1) srange[1] = lower_bound_i(batch, nRows, g + 1);
    __syncthreads();
    const int start = srange[0], end = srange[1];
    if (start >= end) return;
    const float bb = ab2[0];
    const int len = end - start;
    if (len <= 256) {
        const int i = start + t;
        float lg = (i < end) ? p0[i] + p1[i] + bb : -3.402823466e38f;
        red[t] = lg; __syncthreads();
        #pragma unroll
        for (int s = 128; s; s >>= 1) {
            if (t < s) red[t] = fmaxf(red[t], red[t + s]);
            __syncthreads();
        }
        const float m = red[0]; __syncthreads();
        float e = (i < end) ? __expf(lg - m) : 0.f;
        red[t] = e; __syncthreads();
        #pragma unroll
        for (int s = 128; s; s >>= 1) {
            if (t < s) red[t] += red[t + s];
            __syncthreads();
        }
        if (i < end) wout[i] = e / red[0];
    } else {
        float m = -3.402823466e38f;
        for (int i = start + t; i < end; i += 256)
            m = fmaxf(m, p0[i] + p1[i] + bb);
        red[t] = m; __syncthreads();
        #pragma unroll
        for (int s = 128; s; s >>= 1) {
            if (t < s) red[t] = fmaxf(red[t], red[t + s]);
            __syncthreads();
        }
        m = red[0]; __syncthreads();
        float ssum = 0.f;
        for (int i = start + t; i < end; i += 256)
            ssum += __expf(p0[i] + p1[i] + bb - m);
        red[t] = ssum; __syncthreads();
        #pragma unroll
        for (int s = 128; s; s >>= 1) {
            if (t < s) red[t] += red[t + s];
            __syncthreads();
        }
        const float inv = 1.0f / red[0];
        for (int i = start + t; i < end; i += 256)
            wout[i] = __expf(p0[i] + p1[i] + bb - m) * inv;
    }
}

// combine per-tile partials -> out (deterministic fixed-order sum)
__global__ __launch_bounds__(256) void combine_kernel(
    const float* __restrict__ rpart, const int* __restrict__ batch,
    float* __restrict__ out, int nRows)
{
    const int g = blockIdx.x, c = threadIdx.x;
    __shared__ int srange[2];
    if (c == 0) srange[0] = lower_bound_i(batch, nRows, g);
    if (c == 1) srange[1] = lower_bound_i(batch, nRows, g + 1);
    __syncthreads();
    const int lb = srange[0], ub = srange[1];
    float sum = 0.f;
    if (lb < ub) {
        int t0 = lb >> 7, t1 = (ub - 1) >> 7;
        for (int t = t0; t <= t1; t++) {
            int base_row = t << 7;
            int s0 = batch[base_row < nRows ? base_row : nRows - 1];
            int slot = g - s0;
            if (slot == 0 || slot == 1)
                sum += rpart[((size_t)t * 2 + slot) * DIM + c];
        }
    }
    out[(size_t)g * DIM + c] = sum;
}

// ---------------- fused GEMM (R12 shape: 256 thr, 32x64 warp tiles) ---------
// grid(nparts, tiles); blockIdx.x = part (fast -> A L2 reuse).
// SP_ATT: parts 2,3 attention epilogue on B1/bias1.
// rpart != nullptr: weighted-readout epilogue.
template <int SPECIAL>
__global__ __launch_bounds__(256, 2) void gemm_mma(
    const __half* __restrict__ A,
    const __half* __restrict__ B0, const __half* __restrict__ B1,
    const float* __restrict__ bias0, const float* __restrict__ bias1,
    __half* __restrict__ Ch,
    const float* __restrict__ aW2, float* __restrict__ attp,
    const int* __restrict__ batch, const float* __restrict__ wvec,
    float* __restrict__ rpart,
    int nRows, int do_silu)
{
    extern __shared__ char sm[];
    __shared__ float s_bias[BN];
    __shared__ float s_aw2[BN];
    __shared__ float s_part[2][BM];
    __shared__ float s_w[BM];
    __shared__ int   s_seg[BM];
    __shared__ float s_red[2][2][BM];

    const int tid  = threadIdx.x;
    const int wid  = tid >> 5;
    const int lane = tid & 31;
    const int warp_m = wid >> 1;
    const int warp_n = wid & 1;
    const int part = blockIdx.x;
    const bool is_att = (SPECIAL == SP_ATT) && (part >= 2);
    const int colBase = (part & 1) * BN;
    const int rowBase = blockIdx.y * BM;

    const __half* B    = is_att ? B1 : B0;
    const float*  bias = is_att ? bias1 : bias0;

    if (tid < BN) {
        s_bias[tid] = bias[colBase + tid];
        if (is_att) s_aw2[tid] = aW2[colBase + tid];
    }
    if (rpart && tid < BM) {
        int row = rowBase + tid;
        int cr  = row < nRows ? row : nRows - 1;
        s_w[tid]   = (row < nRows) ? wvec[row] : 0.f;
        s_seg[tid] = batch[cr];
    }

    const uint32_t smb = smem_u32(sm);

    auto load_stage = [&](int s, int kt) {
        const uint32_t st = smb + s * STAGE;
        const int ke = kt * BKT;
        #pragma unroll
        for (int i = 0; i < 4; i++) {
            int f = tid + i * 256;
            int r = f >> 3, c = f & 7;
            uint32_t off = (uint32_t)(r * 128 + ((c ^ (r & 7)) << 4));
            int gr = rowBase + r; if (gr >= nRows) gr = nRows - 1;
            cp16(st + off,         A + (size_t)gr * DIM + ke + c * 8);
            cp16(st + OFF_B + off, B + (size_t)(colBase + r) * DIM + ke + c * 8);
        }
        cp_commit();
    };

    load_stage(0, 0);
    load_stage(1, 1);

    float acc[2][8][4];
    #pragma unroll
    for (int mt = 0; mt < 2; mt++)
        #pragma unroll
        for (int j = 0; j < 8; j++)
            #pragma unroll
            for (int q = 0; q < 4; q++) acc[mt][j][q] = 0.f;

    const int rrA = (lane & 7) + ((lane >> 3) & 1) * 8;
    const int khA = lane >> 4;
    const int rrB = (lane & 7) + (lane >> 4) * 8;
    const int khB = (lane >> 3) & 1;

    int sbuf = 0;
    for (int kt = 0; kt < KTILES; kt++) {
        cp_wait<1>();
        __syncthreads();
        if (kt + 2 < KTILES) {
            int ns = sbuf + 2; if (ns >= NSTAGE) ns -= NSTAGE;
            load_stage(ns, kt + 2);
        } else {
            cp_commit();
        }

        const uint32_t ast = smb + sbuf * STAGE;

        #pragma unroll
        for (int ks = 0; ks < 4; ks++) {
            const int cA = ks * 2 + khA;
            const int cB = ks * 2 + khB;
            uint32_t ah[2][4];
            #pragma unroll
            for (int mt = 0; mt < 2; mt++) {
                int row = warp_m * 32 + mt * 16 + rrA;
                ldsm4(ah[mt], ast + row * 128 + ((cA ^ (row & 7)) << 4));
            }
            #pragma unroll
            for (int nt = 0; nt < 4; nt++) {
                int row = warp_n * 64 + nt * 16 + rrB;
                uint32_t bh[4];
                ldsm4(bh, ast + OFF_B + row * 128 + ((cB ^ (row & 7)) << 4));
                #pragma unroll
                for (int mt = 0; mt < 2; mt++)
                    #pragma unroll
                    for (int h = 0; h < 2; h++)
                        mma16816(acc[mt][nt * 2 + h], ah[mt], &bh[h * 2]);
            }
        }
        if (++sbuf >= NSTAGE) sbuf = 0;
    }

    // ---- epilogue ----
    const int g  = lane >> 2;
    const int cp = (lane & 3) * 2;

    if (is_att) {
        float part2[2][2] = {{0.f, 0.f}, {0.f, 0.f}};
        #pragma unroll
        for (int mt = 0; mt < 2; mt++)
            #pragma unroll
            for (int j = 0; j < 8; j++) {
                int lc = warp_n * 64 + j * 8 + cp;
                float bz0 = s_bias[lc], bz1 = s_bias[lc + 1];
                float w0 = s_aw2[lc],  w1 = s_aw2[lc + 1];
                #pragma unroll
                for (int hrow = 0; hrow < 2; hrow++) {
                    float v0 = silu_f(acc[mt][j][hrow * 2]     + bz0);
                    float v1 = silu_f(acc[mt][j][hrow * 2 + 1] + bz1);
                    part2[mt][hrow] += v0 * w0 + v1 * w1;
                }
            }
        #pragma unroll
        for (int mt = 0; mt < 2; mt++)
            #pragma unroll
            for (int hrow = 0; hrow < 2; hrow++) {
                float p = part2[mt][hrow];
                p += __shfl_xor_sync(0xFFFFFFFFu, p, 1);
                p += __shfl_xor_sync(0xFFFFFFFFu, p, 2);
                if ((lane & 3) == 0)
                    s_part[warp_n][warp_m * 32 + mt * 16 + hrow * 8 + g] = p;
            }
        __syncthreads();
        if (tid < BM) {
            int row = rowBase + tid;
            if (row < nRows)
                attp[(size_t)(part - 2) * NMAX + row] =
                    s_part[0][tid] + s_part[1][tid];
        }
        return;
    }

    if (rpart) {
        __syncthreads();
        float* xw = (float*)sm;
        #pragma unroll
        for (int mt = 0; mt < 2; mt++) {
            #pragma unroll
            for (int j = 0; j < 8; j++) {
                int lc = warp_n * 64 + j * 8 + cp;
                float bz0 = s_bias[lc], bz1 = s_bias[lc + 1];
                #pragma unroll
                for (int hrow = 0; hrow < 2; hrow++) {
                    int lr = warp_m * 32 + mt * 16 + hrow * 8 + g;
                    float wv = s_w[lr];
                    xw[lr * XW_STRIDE + lc]     = (acc[mt][j][hrow * 2]     + bz0) * wv;
                    xw[lr * XW_STRIDE + lc + 1] = (acc[mt][j][hrow * 2 + 1] + bz1) * wv;
                }
            }
        }
        __syncthreads();
        int col  = tid & 127;
        int half = tid >> 7;
        int sbase = s_seg[0];
        float a0 = 0.f, a1 = 0.f;
        int r0 = half * 64;
        for (int r = r0; r < r0 + 64; r++) {
            float v = xw[r * XW_STRIDE + col];
            if (s_seg[r] == sbase) a0 += v; else a1 += v;
        }
        s_red[half][0][col] = a0;
        s_red[half][1][col] = a1;
        __syncthreads();
        if (tid < BM) {
            size_t base = ((size_t)blockIdx.y * 2) * DIM + colBase + tid;
            rpart[base]       = s_red[0][0][tid] + s_red[1][0][tid];
            rpart[base + DIM] = s_red[0][1][tid] + s_red[1][1][tid];
        }
        return;
    }

    #pragma unroll
    for (int mt = 0; mt < 2; mt++) {
        int row0 = rowBase + warp_m * 32 + mt * 16 + g;
        #pragma unroll
        for (int j = 0; j < 8; j++) {
            int lc = warp_n * 64 + j * 8 + cp;
            float bz0 = s_bias[lc], bz1 = s_bias[lc + 1];
            #pragma unroll
            for (int hrow = 0; hrow < 2; hrow++) {
                int row = row0 + hrow * 8;
                if (row >= nRows) continue;
                float v0 = acc[mt][j][hrow * 2]     + bz0;
                float v1 = acc[mt][j][hrow * 2 + 1] + bz1;
                if (do_silu) { v0 = silu_f(v0); v1 = silu_f(v1); }
                size_t o = (size_t)row * DIM + colBase + lc;
                *(uint32_t*)(Ch + o) = h2_as_u32(__floats2half2_rn(v0, v1));
            }
        }
    }
}

// ---------------- launch ----------------------------------------------------
extern "C" void kernel_launch(void* const* d_in, const int* in_sizes, int n_in,
                              void* d_out, int out_size)
{
    const float* X     = (const float*)d_in[0];
    const int*   batch = (const int*)d_in[1];
    const float* W1  = (const float*)d_in[3];
    const float* b1  = (const float*)d_in[4];
    const float* W2  = (const float*)d_in[5];
    const float* b2  = (const float*)d_in[6];
    const float* W3  = (const float*)d_in[7];
    const float* b3  = (const float*)d_in[8];
    const float* aW1 = (const float*)d_in[9];
    const float* ab1 = (const float*)d_in[10];
    const float* aW2 = (const float*)d_in[11];
    const float* ab2 = (const float*)d_in[12];
    float* out = (float*)d_out;

    const int N = in_sizes[0] / DIM;
    const int G = out_size / DIM;

    __half *Xh, *h1, *h2, *Wt;
    float *att, *wv, *rp;
    cudaGetSymbolAddress((void**)&Xh, g_Xh);
    cudaGetSymbolAddress((void**)&h1, g_h1);
    cudaGetSymbolAddress((void**)&h2, g_h2);
    cudaGetSymbolAddress((void**)&Wt, g_Wt);
    cudaGetSymbolAddress((void**)&att, g_att);
    cudaGetSymbolAddress((void**)&wv, g_w);
    cudaGetSymbolAddress((void**)&rp, g_rpart);

    __half* W1t = Wt + 0 * DIM * DIM;
    __half* W2t = Wt + 1 * DIM * DIM;
    __half* W3t = Wt + 2 * DIM * DIM;
    __half* WAt = Wt + 3 * DIM * DIM;

    cudaFuncSetAttribute(gemm_mma<SP_ATT>,
                         cudaFuncAttributeMaxDynamicSharedMemorySize, DYN_SMEM);
    cudaFuncSetAttribute(gemm_mma<SP_NONE>,
                         cudaFuncAttributeMaxDynamicSharedMemorySize, DYN_SMEM);

    // prep: X conversion + weight transpose in one launch
    int n4 = N * (DIM / 4);
    prep_kernel<<<1024 + (n4 + 255) / 256, 256>>>(
        (const float4*)X, (uint2*)Xh, n4, W1, W2, W3, aW1, Wt);

    const int tiles = (N + BM - 1) / BM;

    // GEMM1: parts 0,1 -> h1; parts 2,3 -> att partials
    gemm_mma<SP_ATT><<<dim3(4, tiles), 256, DYN_SMEM>>>(
        Xh, W1t, WAt, b1, ab1, h1, aW2, att,
        nullptr, nullptr, nullptr, N, 1);

    // softmax weights (single-pass per segment)
    weights_kernel<<<G, 256>>>(att, att + NMAX, ab2, batch, wv, N);

    // GEMM2: h2 = silu(h1@W2+b2)
    gemm_mma<SP_NONE><<<dim3(2, tiles), 256, DYN_SMEM>>>(
        h1, W2t, W2t, b2, b2, h2, aW2, att,
        nullptr, nullptr, nullptr, N, 1);

    // GEMM3 + fused weighted readout partials
    gemm_mma<SP_NONE><<<dim3(2, tiles), 256, DYN_SMEM>>>(
        h2, W3t, W3t, b3, b3, nullptr, aW2, att,
        batch, wv, rp, N, 0);

    // deterministic combine -> out
    combine_kernel<<<G, 256>>>(rp, batch, out, N);
}